// round 16
// baseline (speedup 1.0000x reference)
#include <cuda_runtime.h>
#include <cuda_fp16.h>
#include <math.h>

// ---------------- problem constants ----------------
constexpr int NN   = 32768;    // total nodes layer1
constexpr int ED   = 262144;   // edges
constexpr int FD   = 256;      // feature dim (4 heads x 64)
constexpr int BT   = 32;       // graphs
constexpr int NPG  = 1024;
constexpr int KP1  = 512;
constexpr int KP2  = 256;
constexpr int N2   = BT * KP1; // 16384 pooled nodes after pool1
constexpr int INDIM = 128;
constexpr int MAXDEG = 64;     // padded CSR width

// ---------------- scratch layout (floats) ----------------
constexpr size_t O_H1    = 0;
constexpr size_t O_OUT1  = O_H1   + (size_t)NN * FD;
constexpr size_t O_ASN1  = O_OUT1 + (size_t)NN * FD;
constexpr size_t O_ADN1  = O_ASN1 + (size_t)NN * 4;
constexpr size_t O_BNS1  = O_ADN1 + (size_t)NN * 4;   // 512
constexpr size_t O_BNS2  = O_BNS1 + 512;              // 512 (adjacent -> one memset)
constexpr size_t O_SC1   = O_BNS2 + 512;
constexpr size_t O_SH1   = O_SC1  + 256;
constexpr size_t O_W1A   = O_SH1  + 256;   // 256 + 1
constexpr size_t O_TANH1 = O_W1A  + 260;
constexpr size_t O_PART  = O_TANH1  + N2;
constexpr size_t O_PART2 = O_PART   + (size_t)BT * 8 * 512;
constexpr size_t O_H2    = O_PART2  + (size_t)BT * 8 * 512;
constexpr size_t O_OUT2  = O_H2     + (size_t)N2 * FD;
constexpr size_t O_ASN2  = O_OUT2   + (size_t)N2 * FD;
constexpr size_t O_ADN2  = O_ASN2   + (size_t)N2 * 4;
constexpr size_t O_SC2   = O_ADN2   + (size_t)N2 * 4;
constexpr size_t O_SH2   = O_SC2    + 256;
constexpr size_t O_W2A   = O_SH2    + 256;
constexpr size_t O_TANH2 = O_W2A    + 260;
constexpr size_t F_TOTAL = O_TANH2  + (size_t)BT * KP2;

__device__ float g_f[F_TOTAL];

constexpr size_t IO_GIDX1 = 0;
constexpr size_t IO_INV1  = IO_GIDX1 + N2;
constexpr size_t IO_GIDX2 = IO_INV1  + NN;
constexpr size_t IO_CSR1  = IO_GIDX2 + (size_t)BT * KP2;
constexpr size_t IO_CSR2  = IO_CSR1  + (size_t)NN * MAXDEG;
constexpr size_t IO_DEG1  = IO_CSR2  + (size_t)N2 * MAXDEG;  // deg1|deg2|cnt adjacent
constexpr size_t IO_DEG2  = IO_DEG1  + NN;
constexpr size_t IO_CNT   = IO_DEG2  + N2;
constexpr size_t I_TOTAL  = IO_CNT   + 8;

__device__ int g_i[I_TOTAL];

// ---------------- fp16x3 helpers ----------------
__device__ __forceinline__ void split_h2(float x, float y, unsigned& hi, unsigned& lo) {
    __half hx = __float2half_rn(x), hy = __float2half_rn(y);
    __half lx = __float2half_rn(x - __half2float(hx));
    __half ly = __float2half_rn(y - __half2float(hy));
    __half2 h2 = __halves2half2(hx, hy);
    __half2 l2 = __halves2half2(lx, ly);
    hi = *(unsigned*)&h2;
    lo = *(unsigned*)&l2;
}
__device__ __forceinline__ void mma_f16(float c[4], const unsigned a[4],
                                        unsigned b0, unsigned b1) {
    asm volatile(
        "mma.sync.aligned.m16n8k16.row.col.f32.f16.f16.f32 "
        "{%0,%1,%2,%3}, {%4,%5,%6,%7}, {%8,%9}, {%0,%1,%2,%3};"
        : "+f"(c[0]), "+f"(c[1]), "+f"(c[2]), "+f"(c[3])
        : "r"(a[0]), "r"(a[1]), "r"(a[2]), "r"(a[3]), "r"(b0), "r"(b1));
}

// ---------------- fp16x3 GEMM (m16n8k16) + fused attention epilogue + optional A-gather ----------------
__global__ __launch_bounds__(256) void sgemm_f16_attn(
    const float* __restrict__ A, const float* __restrict__ B, float* __restrict__ C,
    const float* __restrict__ a_s, const float* __restrict__ a_d,
    float* __restrict__ asn, float* __restrict__ adn, int M, int N, int K,
    const int* __restrict__ gidx_a, const float* __restrict__ asc,
    const float* __restrict__ ash, const float* __restrict__ atv) {
    __shared__ unsigned Ahi[8][136], Alo[8][136];
    __shared__ unsigned Bhi[8][136], Blo[8][136];
    int tid = threadIdx.x, lane = tid & 31, w = tid >> 5;
    int wm = (w >> 1) * 32, wn = (w & 1) * 64;
    int g = lane >> 2, l4 = lane & 3;
    int m0 = blockIdx.y * 128, n0 = blockIdx.x * 128;

    float c[2][8][4];
#pragma unroll
    for (int fm = 0; fm < 2; fm++)
#pragma unroll
        for (int nf = 0; nf < 8; nf++)
#pragma unroll
            for (int i = 0; i < 4; i++) c[fm][nf][i] = 0.f;

    int arow = tid & 127, acol = (tid >> 7) * 8;
    int ak2 = acol >> 1;  // 0 or 4
    int bk2 = tid >> 5, bn = (tid & 31) * 4;
    int srow = m0 + arow;
    float tval = 1.f;
    if (gidx_a) { tval = atv[srow]; srow = gidx_a[srow]; }
    const float* Ap = A + (size_t)srow * K + acol;
    const float* Bp0 = B + (size_t)(2 * bk2) * N + n0 + bn;
    const float* Bp1 = Bp0 + N;

    float4 ra0 = *(const float4*)(Ap);
    float4 ra1 = *(const float4*)(Ap + 4);
    float4 rb0 = *(const float4*)(Bp0);
    float4 rb1 = *(const float4*)(Bp1);

    for (int k0 = 0; k0 < K; k0 += 16) {
        if (gidx_a) {
            float4 s0 = *(const float4*)&asc[k0 + acol];
            float4 s1 = *(const float4*)&asc[k0 + acol + 4];
            float4 h0 = *(const float4*)&ash[k0 + acol];
            float4 h1 = *(const float4*)&ash[k0 + acol + 4];
            ra0.x = (ra0.x * s0.x + h0.x) * tval; ra0.y = (ra0.y * s0.y + h0.y) * tval;
            ra0.z = (ra0.z * s0.z + h0.z) * tval; ra0.w = (ra0.w * s0.w + h0.w) * tval;
            ra1.x = (ra1.x * s1.x + h1.x) * tval; ra1.y = (ra1.y * s1.y + h1.y) * tval;
            ra1.z = (ra1.z * s1.z + h1.z) * tval; ra1.w = (ra1.w * s1.w + h1.w) * tval;
        }
        unsigned hi, lo;
        split_h2(ra0.x, ra0.y, hi, lo); Ahi[ak2 + 0][arow] = hi; Alo[ak2 + 0][arow] = lo;
        split_h2(ra0.z, ra0.w, hi, lo); Ahi[ak2 + 1][arow] = hi; Alo[ak2 + 1][arow] = lo;
        split_h2(ra1.x, ra1.y, hi, lo); Ahi[ak2 + 2][arow] = hi; Alo[ak2 + 2][arow] = lo;
        split_h2(ra1.z, ra1.w, hi, lo); Ahi[ak2 + 3][arow] = hi; Alo[ak2 + 3][arow] = lo;
        split_h2(rb0.x, rb1.x, hi, lo); Bhi[bk2][bn + 0] = hi; Blo[bk2][bn + 0] = lo;
        split_h2(rb0.y, rb1.y, hi, lo); Bhi[bk2][bn + 1] = hi; Blo[bk2][bn + 1] = lo;
        split_h2(rb0.z, rb1.z, hi, lo); Bhi[bk2][bn + 2] = hi; Blo[bk2][bn + 2] = lo;
        split_h2(rb0.w, rb1.w, hi, lo); Bhi[bk2][bn + 3] = hi; Blo[bk2][bn + 3] = lo;
        __syncthreads();
        if (k0 + 16 < K) {
            ra0 = *(const float4*)(Ap + k0 + 16);
            ra1 = *(const float4*)(Ap + k0 + 20);
            rb0 = *(const float4*)(Bp0 + (size_t)(k0 + 16) * N);
            rb1 = *(const float4*)(Bp1 + (size_t)(k0 + 16) * N);
        }
        unsigned ah[2][4], al[2][4];
#pragma unroll
        for (int fm = 0; fm < 2; fm++) {
            int r = wm + fm * 16;
            ah[fm][0] = Ahi[l4][r + g];
            ah[fm][1] = Ahi[l4][r + g + 8];
            ah[fm][2] = Ahi[l4 + 4][r + g];
            ah[fm][3] = Ahi[l4 + 4][r + g + 8];
            al[fm][0] = Alo[l4][r + g];
            al[fm][1] = Alo[l4][r + g + 8];
            al[fm][2] = Alo[l4 + 4][r + g];
            al[fm][3] = Alo[l4 + 4][r + g + 8];
        }
#pragma unroll
        for (int nf = 0; nf < 8; nf++) {
            int nc = wn + nf * 8 + g;
            unsigned bh0 = Bhi[l4][nc];
            unsigned bh1 = Bhi[l4 + 4][nc];
            unsigned bl0 = Blo[l4][nc];
            unsigned bl1 = Blo[l4 + 4][nc];
#pragma unroll
            for (int fm = 0; fm < 2; fm++) {
                mma_f16(c[fm][nf], ah[fm], bh0, bh1);
                mma_f16(c[fm][nf], al[fm], bh0, bh1);
                mma_f16(c[fm][nf], ah[fm], bl0, bl1);
            }
        }
        __syncthreads();
    }

#pragma unroll
    for (int fm = 0; fm < 2; fm++) {
        int r0 = m0 + wm + fm * 16 + g;
#pragma unroll
        for (int nf = 0; nf < 8; nf++) {
            int col = n0 + wn + nf * 8 + 2 * l4;
            *(float2*)&C[(size_t)r0 * N + col]       = make_float2(c[fm][nf][0], c[fm][nf][1]);
            *(float2*)&C[(size_t)(r0 + 8) * N + col] = make_float2(c[fm][nf][2], c[fm][nf][3]);
        }
    }

    int head = (n0 >> 6) + (w & 1);
    float asw0[8], asw1[8], adw0[8], adw1[8];
#pragma unroll
    for (int nf = 0; nf < 8; nf++) {
        int col = head * 64 + nf * 8 + 2 * l4;
        asw0[nf] = a_s[col]; asw1[nf] = a_s[col + 1];
        adw0[nf] = a_d[col]; adw1[nf] = a_d[col + 1];
    }
#pragma unroll
    for (int fm = 0; fm < 2; fm++) {
        float pa0 = 0.f, pa1 = 0.f, pd0 = 0.f, pd1 = 0.f;
#pragma unroll
        for (int nf = 0; nf < 8; nf++) {
            pa0 += c[fm][nf][0] * asw0[nf] + c[fm][nf][1] * asw1[nf];
            pa1 += c[fm][nf][2] * asw0[nf] + c[fm][nf][3] * asw1[nf];
            pd0 += c[fm][nf][0] * adw0[nf] + c[fm][nf][1] * adw1[nf];
            pd1 += c[fm][nf][2] * adw0[nf] + c[fm][nf][3] * adw1[nf];
        }
#pragma unroll
        for (int o = 1; o <= 2; o <<= 1) {
            pa0 += __shfl_xor_sync(~0u, pa0, o);
            pa1 += __shfl_xor_sync(~0u, pa1, o);
            pd0 += __shfl_xor_sync(~0u, pd0, o);
            pd1 += __shfl_xor_sync(~0u, pd1, o);
        }
        if (l4 == 0) {
            int r0 = m0 + wm + fm * 16 + g;
            asn[r0 * 4 + head] = pa0; asn[(r0 + 8) * 4 + head] = pa1;
            adn[r0 * 4 + head] = pd0; adn[(r0 + 8) * 4 + head] = pd1;
        }
    }
}

// ---------------- padded-CSR build ----------------
__global__ void csr_build(const int* __restrict__ src, const int* __restrict__ dst,
                          const int* __restrict__ inv, int* __restrict__ deg,
                          int* __restrict__ csr, int nE) {
    int i = blockIdx.x * blockDim.x + threadIdx.x;
    if (i >= nE) return;
    int s = src[i], d = dst[i];
    if (inv) { s = inv[s]; d = inv[d]; if (s < 0 || d < 0) return; }
    int p = atomicAdd(&deg[d], 1);
    if (p < MAXDEG) csr[(size_t)d * MAXDEG + p] = s;
}

// ---------------- fused GAT gather + BN-finalize tail (last-block pattern) ----------------
__global__ __launch_bounds__(256, 6) void gat_gather(
    const int* __restrict__ csr, const int* __restrict__ deg,
    const float* __restrict__ asn, const float* __restrict__ adn,
    const float* __restrict__ h, const float* __restrict__ bias,
    float* __restrict__ out, float* __restrict__ sums, int n, int upb,
    const float* __restrict__ gw, const float* __restrict__ be,
    const float* __restrict__ pw, float* __restrict__ scale,
    float* __restrict__ shift, float* __restrict__ w1a, float invn,
    int* __restrict__ counter) {
    __shared__ float ssum[512];
    __shared__ float4 sst[8][64];
    __shared__ int lastFlag;
    int t = threadIdx.x;
    ssum[t] = 0.f; ssum[t + 256] = 0.f;
    __syncthreads();
    int lane = t & 31, w = t >> 5;
    int half = (blockIdx.x * upb + w) & 1;
    int c = half * 128 + lane * 4;
    float4 bb = *(const float4*)&bias[c];
    float st[8];
#pragma unroll
    for (int i = 0; i < 8; i++) st[i] = 0.f;

    int base = blockIdx.x * upb;
    int end = base + upb; if (end > 2 * n) end = 2 * n;
    for (int u = base + w; u < end; u += 8) {
        int nd = u >> 1;
        float2 ad = *(const float2*)&adn[(size_t)nd * 4 + half * 2];
        int dg = deg[nd]; if (dg > 63) dg = 63;
        const int* row = csr + (size_t)nd * MAXDEG;
        int sA = (lane < dg) ? row[lane] : nd;
        int sB = (lane + 32 < dg) ? row[lane + 32] : nd;
        bool vA = (lane <= dg);
        bool vB = (lane + 32 <= dg);
        float2 aA = *(const float2*)&asn[(size_t)sA * 4 + half * 2];
        float2 aB = *(const float2*)&asn[(size_t)sB * 4 + half * 2];
        float lA0 = aA.x + ad.x, lA1 = aA.y + ad.y;
        float lB0 = aB.x + ad.x, lB1 = aB.y + ad.y;
        lA0 = lA0 > 0.f ? lA0 : 0.2f * lA0;  lB0 = lB0 > 0.f ? lB0 : 0.2f * lB0;
        lA1 = lA1 > 0.f ? lA1 : 0.2f * lA1;  lB1 = lB1 > 0.f ? lB1 : 0.2f * lB1;
        float pA0 = vA ? __expf(lA0) : 0.f, pA1 = vA ? __expf(lA1) : 0.f;
        float pB0 = vB ? __expf(lB0) : 0.f, pB1 = vB ? __expf(lB1) : 0.f;
        float d0 = pA0 + pB0, d1 = pA1 + pB1;
#pragma unroll
        for (int o = 16; o; o >>= 1) {
            d0 += __shfl_xor_sync(~0u, d0, o);
            d1 += __shfl_xor_sync(~0u, d1, o);
        }
        float r0 = 1.f / d0, r1 = 1.f / d1;
        __syncwarp();
        sst[w][lane]      = make_float4(__int_as_float(sA * FD), pA0 * r0, pA1 * r1, 0.f);
        sst[w][lane + 32] = make_float4(__int_as_float(sB * FD), pB0 * r0, pB1 * r1, 0.f);
        __syncwarp();
        float4 a0 = make_float4(0, 0, 0, 0);
        int ne = dg + 1;
#pragma unroll 4
        for (int e = 0; e < ne; e++) {
            float4 gq = sst[w][e];
            int sofs = __float_as_int(gq.x);
            float p = (lane & 16) ? gq.z : gq.y;
            float4 v = *(const float4*)(h + sofs + c);
            a0.x += p * v.x; a0.y += p * v.y; a0.z += p * v.z; a0.w += p * v.w;
        }
        float o[4];
        o[0] = a0.x + bb.x; o[1] = a0.y + bb.y;
        o[2] = a0.z + bb.z; o[3] = a0.w + bb.w;
#pragma unroll
        for (int i = 0; i < 4; i++) {
            float v = o[i];
            v = 0.5f * v * (1.0f + erff(v * 0.70710678118654752f));
            o[i] = v;
            st[i] += v; st[4 + i] += v * v;
        }
        *(float4*)(out + (size_t)nd * FD + c) = make_float4(o[0], o[1], o[2], o[3]);
    }
#pragma unroll
    for (int i = 0; i < 4; i++) {
        atomicAdd(&ssum[c + i],       st[i]);
        atomicAdd(&ssum[256 + c + i], st[4 + i]);
    }
    __syncthreads();
    atomicAdd(&sums[t],       ssum[t]);
    atomicAdd(&sums[t + 256], ssum[t + 256]);
    __threadfence();
    __syncthreads();
    if (t == 0) lastFlag = (atomicAdd(counter, 1) == (int)gridDim.x - 1) ? 1 : 0;
    __syncthreads();
    if (!lastFlag) return;

    float* red = ssum;
    float* scs = (float*)sst;
    float* shs = scs + 256;
    int f = t;
    float mean = __ldcg(&sums[f]) * invn;
    float var  = __ldcg(&sums[256 + f]) * invn - mean * mean;
    float sc = gw[f] * rsqrtf(var + 1e-5f);
    float sh = be[f] - mean * sc;
    scale[f] = sc; shift[f] = sh;
    scs[f] = sc; shs[f] = sh;
    float pwf = pw[f];
    red[f] = pwf * pwf;
    __syncthreads();
    for (int s = 128; s; s >>= 1) {
        if (f < s) red[f] += red[f + s];
        __syncthreads();
    }
    float pwn = pwf * rsqrtf(red[0]);
    w1a[f] = scs[f] * pwn;
    __syncthreads();
    red[f] = shs[f] * pwn;
    __syncthreads();
    for (int s = 128; s; s >>= 1) {
        if (f < s) red[f] += red[f + s];
        __syncthreads();
    }
    if (f == 0) w1a[256] = red[0];
}

// ---------------- fused pool-score + top-k (block per graph) ----------------
// Each thread computes score(s) for its node(s) (serial 256-dot, weights in smem),
// then 4-pass 8-bit histogram radix select on register-resident keys.
__global__ __launch_bounds__(512) void score_topk(
    const float* __restrict__ x, const float* __restrict__ w1a, int npg, int k,
    int* __restrict__ gidx, float* __restrict__ tv, int* __restrict__ inv) {
    __shared__ float sw[260];
    __shared__ int hist[256];
    __shared__ int sred[16];
    __shared__ unsigned s_prefix;
    __shared__ int s_kneed, s_m;
    __shared__ int ctrG, ctrE;
    int g = blockIdx.x, t = threadIdx.x;
    int lane = t & 31, wid = t >> 5;
    if (t < 260) sw[t] = (t < 257) ? w1a[t] : 0.f;
    __syncthreads();

    // ---- score phase ----
    int e0 = t, e1 = t + 512;
    bool v0 = (e0 < npg), v1 = (e1 < npg);
    float f0 = 0.f, f1 = 0.f;
    {
        const float* r0p = x + ((size_t)g * npg + e0) * FD;
        const float* r1p = x + ((size_t)g * npg + e1) * FD;
        float s0 = 0.f, s1 = 0.f;
#pragma unroll 8
        for (int j = 0; j < 64; j++) {
            float4 wv = *(const float4*)&sw[j * 4];
            if (v0) {
                float4 a = *(const float4*)(r0p + j * 4);
                s0 += a.x * wv.x + a.y * wv.y + a.z * wv.z + a.w * wv.w;
            }
            if (v1) {
                float4 a = *(const float4*)(r1p + j * 4);
                s1 += a.x * wv.x + a.y * wv.y + a.z * wv.z + a.w * wv.w;
            }
        }
        f0 = s0 + sw[256];
        f1 = s1 + sw[256];
    }
    unsigned k0 = 0, k1 = 0;
    if (v0) { unsigned u = __float_as_uint(f0); k0 = (u & 0x80000000u) ? ~u : (u | 0x80000000u); }
    if (v1) { unsigned u = __float_as_uint(f1); k1 = (u & 0x80000000u) ? ~u : (u | 0x80000000u); }
    if (t == 0) { s_prefix = 0; s_kneed = k; }

    // ---- radix select ----
    for (int shift = 24; shift >= 0; shift -= 8) {
        for (int i = t; i < 256; i += 512) hist[i] = 0;
        __syncthreads();
        unsigned pfx = s_prefix;
        int kneed = s_kneed;
        unsigned mask_hi = (shift == 24) ? 0u : (0xFFFFFFFFu << (shift + 8));
        if (v0 && ((k0 ^ pfx) & mask_hi) == 0) atomicAdd(&hist[(k0 >> shift) & 255], 1);
        if (v1 && ((k1 ^ pfx) & mask_hi) == 0) atomicAdd(&hist[(k1 >> shift) & 255], 1);
        __syncthreads();
        if (wid == 0) {
            int bbase = 255 - lane * 8;
            int cb[8];
            int s = 0;
#pragma unroll
            for (int j = 0; j < 8; j++) { cb[j] = hist[bbase - j]; s += cb[j]; }
            int incl = s;
            for (int o = 1; o < 32; o <<= 1) {
                int v = __shfl_up_sync(~0u, incl, o);
                if (lane >= o) incl += v;
            }
            int excl = incl - s;
            bool has = (excl < kneed) && (kneed <= excl + s);
            if (has) {
                int cum = excl, found = -1, rem = 0;
#pragma unroll
                for (int j = 0; j < 8; j++) {
                    if (found < 0 && cum + cb[j] >= kneed) { found = bbase - j; rem = kneed - cum; }
                    cum += cb[j];
                }
                s_prefix = pfx | ((unsigned)found << shift);
                s_kneed = rem;
            }
        }
        __syncthreads();
    }
    unsigned kth = s_prefix;

    {
        int cc = __popc(__ballot_sync(~0u, v0 && k0 > kth))
               + __popc(__ballot_sync(~0u, v1 && k1 > kth));
        if (lane == 0) sred[wid] = cc;
    }
    __syncthreads();
    if (t == 0) {
        int mm = 0;
        for (int i = 0; i < 16; i++) mm += sred[i];
        s_m = mm; ctrG = 0; ctrE = 0;
    }
    __syncthreads();
    int m = s_m, r = k - m;

#pragma unroll
    for (int q = 0; q < 2; q++) {
        bool vv = q ? v1 : v0;
        int e = q ? e1 : e0;
        unsigned kk = q ? k1 : k0;
        float fv = q ? f1 : f0;
        bool selG = vv && kk > kth;
        bool selE = vv && kk == kth;
        unsigned mG = __ballot_sync(~0u, selG);
        unsigned mE = __ballot_sync(~0u, selE);
        int baseG = 0, baseE = 0;
        if (lane == 0) {
            if (mG) baseG = atomicAdd(&ctrG, __popc(mG));
            if (mE) baseE = atomicAdd(&ctrE, __popc(mE));
        }
        baseG = __shfl_sync(~0u, baseG, 0);
        baseE = __shfl_sync(~0u, baseE, 0);
        unsigned lmask = (1u << lane) - 1u;
        int pos = -1;
        if (selG) pos = baseG + __popc(mG & lmask);
        else if (selE) {
            int j = baseE + __popc(mE & lmask);
            if (j < r) pos = m + j;
        }
        if (pos >= 0) {
            int gp = g * k + pos;
            int node = g * npg + e;
            gidx[gp] = node;
            tv[gp] = tanhf(fv);
            if (inv) inv[node] = gp;
        }
    }
}

// ---------------- readout stage 1: per (graph, chunk) partial max/sum ----------------
__global__ void readout_s1(const float* __restrict__ x, const float* __restrict__ sc,
                           const float* __restrict__ sh, const int* __restrict__ gidx,
                           const float* __restrict__ tv, int k, float* __restrict__ partial) {
    int g = blockIdx.x, c = blockIdx.y, f = threadIdx.x;
    int chunk = k / 8;
    int j0 = c * chunk;
    float mx = -1e30f, sm = 0.f;
    float scf = sc[f], shf = sh[f];
    for (int j = j0; j < j0 + chunk; j++) {
        int node = gidx[g * k + j];
        float v = (x[(size_t)node * FD + f] * scf + shf) * tv[g * k + j];
        mx = fmaxf(mx, v);
        sm += v;
    }
    partial[((size_t)(g * 8 + c)) * 512 + f] = mx;
    partial[((size_t)(g * 8 + c)) * 512 + 256 + f] = sm;
}

// ---------------- final: reduce both partials + linear ----------------
__global__ void final_linear(const float* __restrict__ part, const float* __restrict__ part2,
                             const float* __restrict__ Wl, const float* __restrict__ bl,
                             float* __restrict__ out) {
    __shared__ float xr[512];
    int b = blockIdx.x, t = threadIdx.x;
    float mx1 = -1e30f, sm1 = 0.f, mx2 = -1e30f, sm2 = 0.f;
#pragma unroll
    for (int c = 0; c < 8; c++) {
        size_t o1 = ((size_t)(b * 8 + c)) * 512;
        mx1 = fmaxf(mx1, part[o1 + t]);  sm1 += part[o1 + 256 + t];
        mx2 = fmaxf(mx2, part2[o1 + t]); sm2 += part2[o1 + 256 + t];
    }
    xr[t]       = mx1 + mx2;
    xr[t + 256] = sm1 / (float)KP1 + sm2 / (float)KP2;
    __syncthreads();
    float acc = bl[t];
    const float* w = Wl + (size_t)t * 512;
    for (int kk = 0; kk < 512; kk++) acc += xr[kk] * w[kk];
    out[(size_t)b * 256 + t] = acc;
}

// ---------------- host launcher ----------------
extern "C" void kernel_launch(void* const* d_in, const int* in_sizes, int n_in,
                              void* d_out, int out_size) {
    const float* x    = (const float*)d_in[0];
    const int*   ei   = (const int*)d_in[1];
    const int*   src  = ei;
    const int*   dst  = ei + ED;
    const float* W1   = (const float*)d_in[3];
    const float* as1  = (const float*)d_in[4];
    const float* ad1  = (const float*)d_in[5];
    const float* b1   = (const float*)d_in[6];
    const float* g1   = (const float*)d_in[7];
    const float* be1  = (const float*)d_in[8];
    const float* pw1  = (const float*)d_in[9];
    const float* W2   = (const float*)d_in[10];
    const float* as2  = (const float*)d_in[11];
    const float* ad2  = (const float*)d_in[12];
    const float* b2   = (const float*)d_in[13];
    const float* g2   = (const float*)d_in[14];
    const float* be2  = (const float*)d_in[15];
    const float* pw2  = (const float*)d_in[16];
    const float* Wl   = (const float*)d_in[17];
    const float* bl   = (const float*)d_in[18];
    float* out = (float*)d_out;

    float* fb = nullptr;
    int*   ib = nullptr;
    cudaGetSymbolAddress((void**)&fb, g_f);
    cudaGetSymbolAddress((void**)&ib, g_i);

    float* h1    = fb + O_H1;
    float* out1  = fb + O_OUT1;
    float* asn1  = fb + O_ASN1;
    float* adn1  = fb + O_ADN1;
    float* bns1  = fb + O_BNS1;
    float* bns2  = fb + O_BNS2;
    float* sc1   = fb + O_SC1;
    float* sh1   = fb + O_SH1;
    float* w1a   = fb + O_W1A;
    float* tanh1 = fb + O_TANH1;
    float* part  = fb + O_PART;
    float* part2 = fb + O_PART2;
    float* h2    = fb + O_H2;
    float* out2  = fb + O_OUT2;
    float* asn2  = fb + O_ASN2;
    float* adn2  = fb + O_ADN2;
    float* sc2   = fb + O_SC2;
    float* sh2   = fb + O_SH2;
    float* w2a   = fb + O_W2A;
    float* tanh2 = fb + O_TANH2;
    int* gidx1 = ib + IO_GIDX1;
    int* inv1  = ib + IO_INV1;
    int* gidx2 = ib + IO_GIDX2;
    int* csr1  = ib + IO_CSR1;
    int* csr2  = ib + IO_CSR2;
    int* deg1  = ib + IO_DEG1;
    int* deg2  = ib + IO_DEG2;
    int* cnt1  = ib + IO_CNT;
    int* cnt2  = ib + IO_CNT + 1;

    static cudaStream_t s2 = nullptr;
    static cudaEvent_t ev0, ev1, ev2, ev3, ev5;
    if (!s2) {
        cudaStreamCreateWithFlags(&s2, cudaStreamNonBlocking);
        cudaEventCreateWithFlags(&ev0, cudaEventDisableTiming);
        cudaEventCreateWithFlags(&ev1, cudaEventDisableTiming);
        cudaEventCreateWithFlags(&ev2, cudaEventDisableTiming);
        cudaEventCreateWithFlags(&ev3, cudaEventDisableTiming);
        cudaEventCreateWithFlags(&ev5, cudaEventDisableTiming);
    }

    // fork: side stream does memsets + csr_build1 while main does sgemm1
    cudaEventRecord(ev0, 0);
    cudaStreamWaitEvent(s2, ev0, 0);
    cudaMemsetAsync(bns1, 0, 1024 * sizeof(float), s2);                    // bns1|bns2
    cudaMemsetAsync(deg1, 0, (size_t)(NN + N2 + 8) * sizeof(int), s2);     // deg1|deg2|cnt
    cudaMemsetAsync(inv1, 0xFF, (size_t)NN * sizeof(int), s2);
    csr_build<<<(ED + 255) / 256, 256, 0, s2>>>(src, dst, nullptr, deg1, csr1, ED);
    cudaEventRecord(ev1, s2);

    // ---- layer 1 (main stream) ----
    sgemm_f16_attn<<<dim3(FD / 128, NN / 128), 256>>>(x, W1, h1, as1, ad1, asn1, adn1,
                                                      NN, FD, INDIM, nullptr, nullptr, nullptr, nullptr);
    cudaStreamWaitEvent(0, ev1, 0);
    gat_gather<<<2048, 256>>>(csr1, deg1, asn1, adn1, h1, b1, out1, bns1, NN, (2 * NN) / 2048,
                              g1, be1, pw1, sc1, sh1, w1a, 1.0f / NN, cnt1);
    score_topk<<<BT, 512>>>(out1, w1a, NPG, KP1, gidx1, tanh1, inv1);
    cudaEventRecord(ev2, 0);

    // side stream: csr_build2 + layer-1 readout (both need only topk1 results)
    cudaStreamWaitEvent(s2, ev2, 0);
    csr_build<<<(ED + 255) / 256, 256, 0, s2>>>(src, dst, inv1, deg2, csr2, ED);
    cudaEventRecord(ev3, s2);
    readout_s1<<<dim3(BT, 8), 256, 0, s2>>>(out1, sc1, sh1, gidx1, tanh1, KP1, part);
    cudaEventRecord(ev5, s2);

    // ---- layer 2 (main stream): sgemm reads pooled rows via gidx with BN+tanh inline ----
    sgemm_f16_attn<<<dim3(FD / 128, N2 / 128), 256>>>(out1, W2, h2, as2, ad2, asn2, adn2,
                                                      N2, FD, FD, gidx1, sc1, sh1, tanh1);
    cudaStreamWaitEvent(0, ev3, 0);
    gat_gather<<<1024, 256>>>(csr2, deg2, asn2, adn2, h2, b2, out2, bns2, N2, (2 * N2) / 1024,
                              g2, be2, pw2, sc2, sh2, w2a, 1.0f / N2, cnt2);
    score_topk<<<BT, 512>>>(out2, w2a, KP1, KP2, gidx2, tanh2, nullptr);
    readout_s1<<<dim3(BT, 8), 256>>>(out2, sc2, sh2, gidx2, tanh2, KP2, part2);

    // ---- final (join side stream) ----
    cudaStreamWaitEvent(0, ev5, 0);
    final_linear<<<BT, 256>>>(part, part2, Wl, bl, out);
}

// round 17
// speedup vs baseline: 1.1667x; 1.1667x over previous
#include <cuda_runtime.h>
#include <cuda_fp16.h>
#include <math.h>

// ---------------- problem constants ----------------
constexpr int NN   = 32768;    // total nodes layer1
constexpr int ED   = 262144;   // edges
constexpr int FD   = 256;      // feature dim (4 heads x 64)
constexpr int BT   = 32;       // graphs
constexpr int NPG  = 1024;
constexpr int KP1  = 512;
constexpr int KP2  = 256;
constexpr int N2   = BT * KP1; // 16384 pooled nodes after pool1
constexpr int INDIM = 128;
constexpr int MAXDEG = 64;     // padded CSR width

// ---------------- scratch layout (floats) ----------------
constexpr size_t O_H1    = 0;
constexpr size_t O_OUT1  = O_H1   + (size_t)NN * FD;
constexpr size_t O_ASN1  = O_OUT1 + (size_t)NN * FD;
constexpr size_t O_ADN1  = O_ASN1 + (size_t)NN * 4;
constexpr size_t O_BNS1  = O_ADN1 + (size_t)NN * 4;   // 512
constexpr size_t O_BNS2  = O_BNS1 + 512;              // 512 (adjacent -> one memset)
constexpr size_t O_SC1   = O_BNS2 + 512;
constexpr size_t O_SH1   = O_SC1  + 256;
constexpr size_t O_W1A   = O_SH1  + 256;   // 256 + 1
constexpr size_t O_SCORE1= O_W1A  + 260;
constexpr size_t O_TANH1 = O_SCORE1 + NN;
constexpr size_t O_PART  = O_TANH1  + N2;
constexpr size_t O_PART2 = O_PART   + (size_t)BT * 8 * 512;
constexpr size_t O_H2    = O_PART2  + (size_t)BT * 8 * 512;
constexpr size_t O_OUT2  = O_H2     + (size_t)N2 * FD;
constexpr size_t O_ASN2  = O_OUT2   + (size_t)N2 * FD;
constexpr size_t O_ADN2  = O_ASN2   + (size_t)N2 * 4;
constexpr size_t O_SC2   = O_ADN2   + (size_t)N2 * 4;
constexpr size_t O_SH2   = O_SC2    + 256;
constexpr size_t O_W2A   = O_SH2    + 256;
constexpr size_t O_SCORE2= O_W2A    + 260;
constexpr size_t O_TANH2 = O_SCORE2 + N2;
constexpr size_t F_TOTAL = O_TANH2  + (size_t)BT * KP2;

__device__ float g_f[F_TOTAL];

constexpr size_t IO_GIDX1 = 0;
constexpr size_t IO_INV1  = IO_GIDX1 + N2;
constexpr size_t IO_GIDX2 = IO_INV1  + NN;
constexpr size_t IO_CSR1  = IO_GIDX2 + (size_t)BT * KP2;
constexpr size_t IO_CSR2  = IO_CSR1  + (size_t)NN * MAXDEG;
constexpr size_t IO_DEG1  = IO_CSR2  + (size_t)N2 * MAXDEG;  // deg1|deg2|cnt adjacent
constexpr size_t IO_DEG2  = IO_DEG1  + NN;
constexpr size_t IO_CNT   = IO_DEG2  + N2;
constexpr size_t I_TOTAL  = IO_CNT   + 8;

__device__ int g_i[I_TOTAL];

// ---------------- fp16x3 helpers ----------------
__device__ __forceinline__ void split_h2(float x, float y, unsigned& hi, unsigned& lo) {
    __half hx = __float2half_rn(x), hy = __float2half_rn(y);
    __half lx = __float2half_rn(x - __half2float(hx));
    __half ly = __float2half_rn(y - __half2float(hy));
    __half2 h2 = __halves2half2(hx, hy);
    __half2 l2 = __halves2half2(lx, ly);
    hi = *(unsigned*)&h2;
    lo = *(unsigned*)&l2;
}
__device__ __forceinline__ void mma_f16(float c[4], const unsigned a[4],
                                        unsigned b0, unsigned b1) {
    asm volatile(
        "mma.sync.aligned.m16n8k16.row.col.f32.f16.f16.f32 "
        "{%0,%1,%2,%3}, {%4,%5,%6,%7}, {%8,%9}, {%0,%1,%2,%3};"
        : "+f"(c[0]), "+f"(c[1]), "+f"(c[2]), "+f"(c[3])
        : "r"(a[0]), "r"(a[1]), "r"(a[2]), "r"(a[3]), "r"(b0), "r"(b1));
}

// ---------------- fp16x3 GEMM (m16n8k16) + fused attention epilogue + optional A-gather ----------------
__global__ __launch_bounds__(256) void sgemm_f16_attn(
    const float* __restrict__ A, const float* __restrict__ B, float* __restrict__ C,
    const float* __restrict__ a_s, const float* __restrict__ a_d,
    float* __restrict__ asn, float* __restrict__ adn, int M, int N, int K,
    const int* __restrict__ gidx_a, const float* __restrict__ asc,
    const float* __restrict__ ash, const float* __restrict__ atv) {
    __shared__ unsigned Ahi[8][136], Alo[8][136];
    __shared__ unsigned Bhi[8][136], Blo[8][136];
    int tid = threadIdx.x, lane = tid & 31, w = tid >> 5;
    int wm = (w >> 1) * 32, wn = (w & 1) * 64;
    int g = lane >> 2, l4 = lane & 3;
    int m0 = blockIdx.y * 128, n0 = blockIdx.x * 128;

    float c[2][8][4];
#pragma unroll
    for (int fm = 0; fm < 2; fm++)
#pragma unroll
        for (int nf = 0; nf < 8; nf++)
#pragma unroll
            for (int i = 0; i < 4; i++) c[fm][nf][i] = 0.f;

    int arow = tid & 127, acol = (tid >> 7) * 8;
    int ak2 = acol >> 1;  // 0 or 4
    int bk2 = tid >> 5, bn = (tid & 31) * 4;
    int srow = m0 + arow;
    float tval = 1.f;
    if (gidx_a) { tval = atv[srow]; srow = gidx_a[srow]; }
    const float* Ap = A + (size_t)srow * K + acol;
    const float* Bp0 = B + (size_t)(2 * bk2) * N + n0 + bn;
    const float* Bp1 = Bp0 + N;

    float4 ra0 = *(const float4*)(Ap);
    float4 ra1 = *(const float4*)(Ap + 4);
    float4 rb0 = *(const float4*)(Bp0);
    float4 rb1 = *(const float4*)(Bp1);

    for (int k0 = 0; k0 < K; k0 += 16) {
        if (gidx_a) {
            float4 s0 = *(const float4*)&asc[k0 + acol];
            float4 s1 = *(const float4*)&asc[k0 + acol + 4];
            float4 h0 = *(const float4*)&ash[k0 + acol];
            float4 h1 = *(const float4*)&ash[k0 + acol + 4];
            ra0.x = (ra0.x * s0.x + h0.x) * tval; ra0.y = (ra0.y * s0.y + h0.y) * tval;
            ra0.z = (ra0.z * s0.z + h0.z) * tval; ra0.w = (ra0.w * s0.w + h0.w) * tval;
            ra1.x = (ra1.x * s1.x + h1.x) * tval; ra1.y = (ra1.y * s1.y + h1.y) * tval;
            ra1.z = (ra1.z * s1.z + h1.z) * tval; ra1.w = (ra1.w * s1.w + h1.w) * tval;
        }
        unsigned hi, lo;
        split_h2(ra0.x, ra0.y, hi, lo); Ahi[ak2 + 0][arow] = hi; Alo[ak2 + 0][arow] = lo;
        split_h2(ra0.z, ra0.w, hi, lo); Ahi[ak2 + 1][arow] = hi; Alo[ak2 + 1][arow] = lo;
        split_h2(ra1.x, ra1.y, hi, lo); Ahi[ak2 + 2][arow] = hi; Alo[ak2 + 2][arow] = lo;
        split_h2(ra1.z, ra1.w, hi, lo); Ahi[ak2 + 3][arow] = hi; Alo[ak2 + 3][arow] = lo;
        split_h2(rb0.x, rb1.x, hi, lo); Bhi[bk2][bn + 0] = hi; Blo[bk2][bn + 0] = lo;
        split_h2(rb0.y, rb1.y, hi, lo); Bhi[bk2][bn + 1] = hi; Blo[bk2][bn + 1] = lo;
        split_h2(rb0.z, rb1.z, hi, lo); Bhi[bk2][bn + 2] = hi; Blo[bk2][bn + 2] = lo;
        split_h2(rb0.w, rb1.w, hi, lo); Bhi[bk2][bn + 3] = hi; Blo[bk2][bn + 3] = lo;
        __syncthreads();
        if (k0 + 16 < K) {
            ra0 = *(const float4*)(Ap + k0 + 16);
            ra1 = *(const float4*)(Ap + k0 + 20);
            rb0 = *(const float4*)(Bp0 + (size_t)(k0 + 16) * N);
            rb1 = *(const float4*)(Bp1 + (size_t)(k0 + 16) * N);
        }
        unsigned ah[2][4], al[2][4];
#pragma unroll
        for (int fm = 0; fm < 2; fm++) {
            int r = wm + fm * 16;
            ah[fm][0] = Ahi[l4][r + g];
            ah[fm][1] = Ahi[l4][r + g + 8];
            ah[fm][2] = Ahi[l4 + 4][r + g];
            ah[fm][3] = Ahi[l4 + 4][r + g + 8];
            al[fm][0] = Alo[l4][r + g];
            al[fm][1] = Alo[l4][r + g + 8];
            al[fm][2] = Alo[l4 + 4][r + g];
            al[fm][3] = Alo[l4 + 4][r + g + 8];
        }
#pragma unroll
        for (int nf = 0; nf < 8; nf++) {
            int nc = wn + nf * 8 + g;
            unsigned bh0 = Bhi[l4][nc];
            unsigned bh1 = Bhi[l4 + 4][nc];
            unsigned bl0 = Blo[l4][nc];
            unsigned bl1 = Blo[l4 + 4][nc];
#pragma unroll
            for (int fm = 0; fm < 2; fm++) {
                mma_f16(c[fm][nf], ah[fm], bh0, bh1);
                mma_f16(c[fm][nf], al[fm], bh0, bh1);
                mma_f16(c[fm][nf], ah[fm], bl0, bl1);
            }
        }
        __syncthreads();
    }

#pragma unroll
    for (int fm = 0; fm < 2; fm++) {
        int r0 = m0 + wm + fm * 16 + g;
#pragma unroll
        for (int nf = 0; nf < 8; nf++) {
            int col = n0 + wn + nf * 8 + 2 * l4;
            *(float2*)&C[(size_t)r0 * N + col]       = make_float2(c[fm][nf][0], c[fm][nf][1]);
            *(float2*)&C[(size_t)(r0 + 8) * N + col] = make_float2(c[fm][nf][2], c[fm][nf][3]);
        }
    }

    int head = (n0 >> 6) + (w & 1);
    float asw0[8], asw1[8], adw0[8], adw1[8];
#pragma unroll
    for (int nf = 0; nf < 8; nf++) {
        int col = head * 64 + nf * 8 + 2 * l4;
        asw0[nf] = a_s[col]; asw1[nf] = a_s[col + 1];
        adw0[nf] = a_d[col]; adw1[nf] = a_d[col + 1];
    }
#pragma unroll
    for (int fm = 0; fm < 2; fm++) {
        float pa0 = 0.f, pa1 = 0.f, pd0 = 0.f, pd1 = 0.f;
#pragma unroll
        for (int nf = 0; nf < 8; nf++) {
            pa0 += c[fm][nf][0] * asw0[nf] + c[fm][nf][1] * asw1[nf];
            pa1 += c[fm][nf][2] * asw0[nf] + c[fm][nf][3] * asw1[nf];
            pd0 += c[fm][nf][0] * adw0[nf] + c[fm][nf][1] * adw1[nf];
            pd1 += c[fm][nf][2] * adw0[nf] + c[fm][nf][3] * adw1[nf];
        }
#pragma unroll
        for (int o = 1; o <= 2; o <<= 1) {
            pa0 += __shfl_xor_sync(~0u, pa0, o);
            pa1 += __shfl_xor_sync(~0u, pa1, o);
            pd0 += __shfl_xor_sync(~0u, pd0, o);
            pd1 += __shfl_xor_sync(~0u, pd1, o);
        }
        if (l4 == 0) {
            int r0 = m0 + wm + fm * 16 + g;
            asn[r0 * 4 + head] = pa0; asn[(r0 + 8) * 4 + head] = pa1;
            adn[r0 * 4 + head] = pd0; adn[(r0 + 8) * 4 + head] = pd1;
        }
    }
}

// ---------------- padded-CSR build ----------------
__global__ void csr_build(const int* __restrict__ src, const int* __restrict__ dst,
                          const int* __restrict__ inv, int* __restrict__ deg,
                          int* __restrict__ csr, int nE) {
    int i = blockIdx.x * blockDim.x + threadIdx.x;
    if (i >= nE) return;
    int s = src[i], d = dst[i];
    if (inv) { s = inv[s]; d = inv[d]; if (s < 0 || d < 0) return; }
    int p = atomicAdd(&deg[d], 1);
    if (p < MAXDEG) csr[(size_t)d * MAXDEG + p] = s;
}

// ---------------- fused GAT gather + BN-finalize tail (last-block pattern) ----------------
__global__ __launch_bounds__(256, 6) void gat_gather(
    const int* __restrict__ csr, const int* __restrict__ deg,
    const float* __restrict__ asn, const float* __restrict__ adn,
    const float* __restrict__ h, const float* __restrict__ bias,
    float* __restrict__ out, float* __restrict__ sums, int n, int upb,
    const float* __restrict__ gw, const float* __restrict__ be,
    const float* __restrict__ pw, float* __restrict__ scale,
    float* __restrict__ shift, float* __restrict__ w1a, float invn,
    int* __restrict__ counter) {
    __shared__ float ssum[512];
    __shared__ float4 sst[8][64];
    __shared__ int lastFlag;
    int t = threadIdx.x;
    ssum[t] = 0.f; ssum[t + 256] = 0.f;
    __syncthreads();
    int lane = t & 31, w = t >> 5;
    int half = (blockIdx.x * upb + w) & 1;
    int c = half * 128 + lane * 4;
    float4 bb = *(const float4*)&bias[c];
    float st[8];
#pragma unroll
    for (int i = 0; i < 8; i++) st[i] = 0.f;

    int base = blockIdx.x * upb;
    int end = base + upb; if (end > 2 * n) end = 2 * n;
    for (int u = base + w; u < end; u += 8) {
        int nd = u >> 1;
        float2 ad = *(const float2*)&adn[(size_t)nd * 4 + half * 2];
        int dg = deg[nd]; if (dg > 63) dg = 63;
        const int* row = csr + (size_t)nd * MAXDEG;
        int sA = (lane < dg) ? row[lane] : nd;
        int sB = (lane + 32 < dg) ? row[lane + 32] : nd;
        bool vA = (lane <= dg);
        bool vB = (lane + 32 <= dg);
        float2 aA = *(const float2*)&asn[(size_t)sA * 4 + half * 2];
        float2 aB = *(const float2*)&asn[(size_t)sB * 4 + half * 2];
        float lA0 = aA.x + ad.x, lA1 = aA.y + ad.y;
        float lB0 = aB.x + ad.x, lB1 = aB.y + ad.y;
        lA0 = lA0 > 0.f ? lA0 : 0.2f * lA0;  lB0 = lB0 > 0.f ? lB0 : 0.2f * lB0;
        lA1 = lA1 > 0.f ? lA1 : 0.2f * lA1;  lB1 = lB1 > 0.f ? lB1 : 0.2f * lB1;
        float pA0 = vA ? __expf(lA0) : 0.f, pA1 = vA ? __expf(lA1) : 0.f;
        float pB0 = vB ? __expf(lB0) : 0.f, pB1 = vB ? __expf(lB1) : 0.f;
        float d0 = pA0 + pB0, d1 = pA1 + pB1;
#pragma unroll
        for (int o = 16; o; o >>= 1) {
            d0 += __shfl_xor_sync(~0u, d0, o);
            d1 += __shfl_xor_sync(~0u, d1, o);
        }
        float r0 = 1.f / d0, r1 = 1.f / d1;
        __syncwarp();
        sst[w][lane]      = make_float4(__int_as_float(sA * FD), pA0 * r0, pA1 * r1, 0.f);
        sst[w][lane + 32] = make_float4(__int_as_float(sB * FD), pB0 * r0, pB1 * r1, 0.f);
        __syncwarp();
        float4 a0 = make_float4(0, 0, 0, 0);
        int ne = dg + 1;
#pragma unroll 4
        for (int e = 0; e < ne; e++) {
            float4 gq = sst[w][e];
            int sofs = __float_as_int(gq.x);
            float p = (lane & 16) ? gq.z : gq.y;
            float4 v = *(const float4*)(h + sofs + c);
            a0.x += p * v.x; a0.y += p * v.y; a0.z += p * v.z; a0.w += p * v.w;
        }
        float o[4];
        o[0] = a0.x + bb.x; o[1] = a0.y + bb.y;
        o[2] = a0.z + bb.z; o[3] = a0.w + bb.w;
#pragma unroll
        for (int i = 0; i < 4; i++) {
            float v = o[i];
            v = 0.5f * v * (1.0f + erff(v * 0.70710678118654752f));
            o[i] = v;
            st[i] += v; st[4 + i] += v * v;
        }
        *(float4*)(out + (size_t)nd * FD + c) = make_float4(o[0], o[1], o[2], o[3]);
    }
#pragma unroll
    for (int i = 0; i < 4; i++) {
        atomicAdd(&ssum[c + i],       st[i]);
        atomicAdd(&ssum[256 + c + i], st[4 + i]);
    }
    __syncthreads();
    atomicAdd(&sums[t],       ssum[t]);
    atomicAdd(&sums[t + 256], ssum[t + 256]);
    __threadfence();
    __syncthreads();
    if (t == 0) lastFlag = (atomicAdd(counter, 1) == (int)gridDim.x - 1) ? 1 : 0;
    __syncthreads();
    if (!lastFlag) return;

    float* red = ssum;
    float* scs = (float*)sst;
    float* shs = scs + 256;
    int f = t;
    float mean = __ldcg(&sums[f]) * invn;
    float var  = __ldcg(&sums[256 + f]) * invn - mean * mean;
    float sc = gw[f] * rsqrtf(var + 1e-5f);
    float sh = be[f] - mean * sc;
    scale[f] = sc; shift[f] = sh;
    scs[f] = sc; shs[f] = sh;
    float pwf = pw[f];
    red[f] = pwf * pwf;
    __syncthreads();
    for (int s = 128; s; s >>= 1) {
        if (f < s) red[f] += red[f + s];
        __syncthreads();
    }
    float pwn = pwf * rsqrtf(red[0]);
    w1a[f] = scs[f] * pwn;
    __syncthreads();
    red[f] = shs[f] * pwn;
    __syncthreads();
    for (int s = 128; s; s >>= 1) {
        if (f < s) red[f] += red[f + s];
        __syncthreads();
    }
    if (f == 0) w1a[256] = red[0];
}

// ---------------- pool score: dot(x, w1) + w0, 4 nodes per warp ----------------
__global__ void pool_score(const float* __restrict__ x, const float* __restrict__ w1a,
                           float* __restrict__ score, int n) {
    int wbase = ((blockIdx.x * blockDim.x + threadIdx.x) >> 5) * 4;
    int lane = threadIdx.x & 31;
    if (wbase >= n) return;
    int c0 = lane * 4, c1 = c0 + 128;
    float4 p0 = *(const float4*)&w1a[c0], p1 = *(const float4*)&w1a[c1];
    float w0 = w1a[256];
    float s[4];
#pragma unroll
    for (int i = 0; i < 4; i++) {
        const float* row = x + (size_t)(wbase + i) * FD;
        float4 v0 = __ldcs((const float4*)(row + c0));
        float4 v1 = __ldcs((const float4*)(row + c1));
        s[i] = v0.x * p0.x + v0.y * p0.y + v0.z * p0.z + v0.w * p0.w
             + v1.x * p1.x + v1.y * p1.y + v1.z * p1.z + v1.w * p1.w;
    }
#pragma unroll
    for (int o = 16; o; o >>= 1) {
        s[0] += __shfl_down_sync(~0u, s[0], o);
        s[1] += __shfl_down_sync(~0u, s[1], o);
        s[2] += __shfl_down_sync(~0u, s[2], o);
        s[3] += __shfl_down_sync(~0u, s[3], o);
    }
    if (lane == 0) {
#pragma unroll
        for (int i = 0; i < 4; i++) score[wbase + i] = s[i] + w0;
    }
}

// ---------------- per-graph top-k: 4-pass 8-bit histogram radix select ----------------
__global__ __launch_bounds__(512) void topk_select(
    const float* __restrict__ score, int npg, int k,
    int* __restrict__ gidx, float* __restrict__ tv, int* __restrict__ inv) {
    __shared__ int hist[256];
    __shared__ int sred[16];
    __shared__ unsigned s_prefix;
    __shared__ int s_kneed, s_m;
    __shared__ int ctrG, ctrE;
    int g = blockIdx.x, t = threadIdx.x;
    int lane = t & 31, wid = t >> 5;
    const float* sg = score + (size_t)g * npg;
    int e0 = t, e1 = t + 512;
    bool v0 = (e0 < npg), v1 = (e1 < npg);
    float f0 = v0 ? sg[e0] : 0.f, f1 = v1 ? sg[e1] : 0.f;
    unsigned k0 = 0, k1 = 0;
    if (v0) { unsigned u = __float_as_uint(f0); k0 = (u & 0x80000000u) ? ~u : (u | 0x80000000u); }
    if (v1) { unsigned u = __float_as_uint(f1); k1 = (u & 0x80000000u) ? ~u : (u | 0x80000000u); }
    if (t == 0) { s_prefix = 0; s_kneed = k; }

    for (int shift = 24; shift >= 0; shift -= 8) {
        for (int i = t; i < 256; i += 512) hist[i] = 0;
        __syncthreads();
        unsigned pfx = s_prefix;
        int kneed = s_kneed;
        unsigned mask_hi = (shift == 24) ? 0u : (0xFFFFFFFFu << (shift + 8));
        if (v0 && ((k0 ^ pfx) & mask_hi) == 0) atomicAdd(&hist[(k0 >> shift) & 255], 1);
        if (v1 && ((k1 ^ pfx) & mask_hi) == 0) atomicAdd(&hist[(k1 >> shift) & 255], 1);
        __syncthreads();
        if (wid == 0) {
            int bbase = 255 - lane * 8;
            int cb[8];
            int s = 0;
#pragma unroll
            for (int j = 0; j < 8; j++) { cb[j] = hist[bbase - j]; s += cb[j]; }
            int incl = s;
            for (int o = 1; o < 32; o <<= 1) {
                int v = __shfl_up_sync(~0u, incl, o);
                if (lane >= o) incl += v;
            }
            int excl = incl - s;
            bool has = (excl < kneed) && (kneed <= excl + s);
            if (has) {
                int cum = excl, found = -1, rem = 0;
#pragma unroll
                for (int j = 0; j < 8; j++) {
                    if (found < 0 && cum + cb[j] >= kneed) { found = bbase - j; rem = kneed - cum; }
                    cum += cb[j];
                }
                s_prefix = pfx | ((unsigned)found << shift);
                s_kneed = rem;
            }
        }
        __syncthreads();
    }
    unsigned kth = s_prefix;

    {
        int cc = __popc(__ballot_sync(~0u, v0 && k0 > kth))
               + __popc(__ballot_sync(~0u, v1 && k1 > kth));
        if (lane == 0) sred[wid] = cc;
    }
    __syncthreads();
    if (t == 0) {
        int mm = 0;
        for (int i = 0; i < 16; i++) mm += sred[i];
        s_m = mm; ctrG = 0; ctrE = 0;
    }
    __syncthreads();
    int m = s_m, r = k - m;

#pragma unroll
    for (int q = 0; q < 2; q++) {
        bool vv = q ? v1 : v0;
        int e = q ? e1 : e0;
        unsigned kk = q ? k1 : k0;
        float fv = q ? f1 : f0;
        bool selG = vv && kk > kth;
        bool selE = vv && kk == kth;
        unsigned mG = __ballot_sync(~0u, selG);
        unsigned mE = __ballot_sync(~0u, selE);
        int baseG = 0, baseE = 0;
        if (lane == 0) {
            if (mG) baseG = atomicAdd(&ctrG, __popc(mG));
            if (mE) baseE = atomicAdd(&ctrE, __popc(mE));
        }
        baseG = __shfl_sync(~0u, baseG, 0);
        baseE = __shfl_sync(~0u, baseE, 0);
        unsigned lmask = (1u << lane) - 1u;
        int pos = -1;
        if (selG) pos = baseG + __popc(mG & lmask);
        else if (selE) {
            int j = baseE + __popc(mE & lmask);
            if (j < r) pos = m + j;
        }
        if (pos >= 0) {
            int gp = g * k + pos;
            int node = g * npg + e;
            gidx[gp] = node;
            tv[gp] = tanhf(fv);
            if (inv) inv[node] = gp;
        }
    }
}

// ---------------- readout stage 1: per (graph, chunk) partial max/sum ----------------
__global__ void readout_s1(const float* __restrict__ x, const float* __restrict__ sc,
                           const float* __restrict__ sh, const int* __restrict__ gidx,
                           const float* __restrict__ tv, int k, float* __restrict__ partial) {
    int g = blockIdx.x, c = blockIdx.y, f = threadIdx.x;
    int chunk = k / 8;
    int j0 = c * chunk;
    float mx = -1e30f, sm = 0.f;
    float scf = sc[f], shf = sh[f];
    for (int j = j0; j < j0 + chunk; j++) {
        int node = gidx[g * k + j];
        float v = (__ldcs(&x[(size_t)node * FD + f]) * scf + shf) * tv[g * k + j];
        mx = fmaxf(mx, v);
        sm += v;
    }
    partial[((size_t)(g * 8 + c)) * 512 + f] = mx;
    partial[((size_t)(g * 8 + c)) * 512 + 256 + f] = sm;
}

// ---------------- final: reduce both partials + linear ----------------
__global__ void final_linear(const float* __restrict__ part, const float* __restrict__ part2,
                             const float* __restrict__ Wl, const float* __restrict__ bl,
                             float* __restrict__ out) {
    __shared__ float xr[512];
    int b = blockIdx.x, t = threadIdx.x;
    float mx1 = -1e30f, sm1 = 0.f, mx2 = -1e30f, sm2 = 0.f;
#pragma unroll
    for (int c = 0; c < 8; c++) {
        size_t o1 = ((size_t)(b * 8 + c)) * 512;
        mx1 = fmaxf(mx1, part[o1 + t]);  sm1 += part[o1 + 256 + t];
        mx2 = fmaxf(mx2, part2[o1 + t]); sm2 += part2[o1 + 256 + t];
    }
    xr[t]       = mx1 + mx2;
    xr[t + 256] = sm1 / (float)KP1 + sm2 / (float)KP2;
    __syncthreads();
    float acc = bl[t];
    const float* w = Wl + (size_t)t * 512;
    for (int kk = 0; kk < 512; kk++) acc += xr[kk] * w[kk];
    out[(size_t)b * 256 + t] = acc;
}

// ---------------- host launcher ----------------
extern "C" void kernel_launch(void* const* d_in, const int* in_sizes, int n_in,
                              void* d_out, int out_size) {
    const float* x    = (const float*)d_in[0];
    const int*   ei   = (const int*)d_in[1];
    const int*   src  = ei;
    const int*   dst  = ei + ED;
    const float* W1   = (const float*)d_in[3];
    const float* as1  = (const float*)d_in[4];
    const float* ad1  = (const float*)d_in[5];
    const float* b1   = (const float*)d_in[6];
    const float* g1   = (const float*)d_in[7];
    const float* be1  = (const float*)d_in[8];
    const float* pw1  = (const float*)d_in[9];
    const float* W2   = (const float*)d_in[10];
    const float* as2  = (const float*)d_in[11];
    const float* ad2  = (const float*)d_in[12];
    const float* b2   = (const float*)d_in[13];
    const float* g2   = (const float*)d_in[14];
    const float* be2  = (const float*)d_in[15];
    const float* pw2  = (const float*)d_in[16];
    const float* Wl   = (const float*)d_in[17];
    const float* bl   = (const float*)d_in[18];
    float* out = (float*)d_out;

    float* fb = nullptr;
    int*   ib = nullptr;
    cudaGetSymbolAddress((void**)&fb, g_f);
    cudaGetSymbolAddress((void**)&ib, g_i);

    float* h1    = fb + O_H1;
    float* out1  = fb + O_OUT1;
    float* asn1  = fb + O_ASN1;
    float* adn1  = fb + O_ADN1;
    float* bns1  = fb + O_BNS1;
    float* bns2  = fb + O_BNS2;
    float* sc1   = fb + O_SC1;
    float* sh1   = fb + O_SH1;
    float* w1a   = fb + O_W1A;
    float* score1= fb + O_SCORE1;
    float* tanh1 = fb + O_TANH1;
    float* part  = fb + O_PART;
    float* part2 = fb + O_PART2;
    float* h2    = fb + O_H2;
    float* out2  = fb + O_OUT2;
    float* asn2  = fb + O_ASN2;
    float* adn2  = fb + O_ADN2;
    float* sc2   = fb + O_SC2;
    float* sh2   = fb + O_SH2;
    float* w2a   = fb + O_W2A;
    float* score2= fb + O_SCORE2;
    float* tanh2 = fb + O_TANH2;
    int* gidx1 = ib + IO_GIDX1;
    int* inv1  = ib + IO_INV1;
    int* gidx2 = ib + IO_GIDX2;
    int* csr1  = ib + IO_CSR1;
    int* csr2  = ib + IO_CSR2;
    int* deg1  = ib + IO_DEG1;
    int* deg2  = ib + IO_DEG2;
    int* cnt1  = ib + IO_CNT;
    int* cnt2  = ib + IO_CNT + 1;

    static cudaStream_t s2 = nullptr;
    static cudaEvent_t ev0, ev1, ev2, ev3, ev5;
    if (!s2) {
        cudaStreamCreateWithFlags(&s2, cudaStreamNonBlocking);
        cudaEventCreateWithFlags(&ev0, cudaEventDisableTiming);
        cudaEventCreateWithFlags(&ev1, cudaEventDisableTiming);
        cudaEventCreateWithFlags(&ev2, cudaEventDisableTiming);
        cudaEventCreateWithFlags(&ev3, cudaEventDisableTiming);
        cudaEventCreateWithFlags(&ev5, cudaEventDisableTiming);
    }

    // fork: side stream does memsets + csr_build1 while main does sgemm1
    cudaEventRecord(ev0, 0);
    cudaStreamWaitEvent(s2, ev0, 0);
    cudaMemsetAsync(bns1, 0, 1024 * sizeof(float), s2);                    // bns1|bns2
    cudaMemsetAsync(deg1, 0, (size_t)(NN + N2 + 8) * sizeof(int), s2);     // deg1|deg2|cnt
    cudaMemsetAsync(inv1, 0xFF, (size_t)NN * sizeof(int), s2);
    csr_build<<<(ED + 255) / 256, 256, 0, s2>>>(src, dst, nullptr, deg1, csr1, ED);
    cudaEventRecord(ev1, s2);

    // ---- layer 1 (main stream) ----
    sgemm_f16_attn<<<dim3(FD / 128, NN / 128), 256>>>(x, W1, h1, as1, ad1, asn1, adn1,
                                                      NN, FD, INDIM, nullptr, nullptr, nullptr, nullptr);
    cudaStreamWaitEvent(0, ev1, 0);
    gat_gather<<<2048, 256>>>(csr1, deg1, asn1, adn1, h1, b1, out1, bns1, NN, (2 * NN) / 2048,
                              g1, be1, pw1, sc1, sh1, w1a, 1.0f / NN, cnt1);
    pool_score<<<NN / 32, 256>>>(out1, w1a, score1, NN);
    topk_select<<<BT, 512>>>(score1, NPG, KP1, gidx1, tanh1, inv1);
    cudaEventRecord(ev2, 0);

    // side stream: csr_build2 + layer-1 readout (both need only topk1 results)
    cudaStreamWaitEvent(s2, ev2, 0);
    csr_build<<<(ED + 255) / 256, 256, 0, s2>>>(src, dst, inv1, deg2, csr2, ED);
    cudaEventRecord(ev3, s2);
    readout_s1<<<dim3(BT, 8), 256, 0, s2>>>(out1, sc1, sh1, gidx1, tanh1, KP1, part);
    cudaEventRecord(ev5, s2);

    // ---- layer 2 (main stream): sgemm reads pooled rows via gidx with BN+tanh inline ----
    sgemm_f16_attn<<<dim3(FD / 128, N2 / 128), 256>>>(out1, W2, h2, as2, ad2, asn2, adn2,
                                                      N2, FD, FD, gidx1, sc1, sh1, tanh1);
    cudaStreamWaitEvent(0, ev3, 0);
    gat_gather<<<1024, 256>>>(csr2, deg2, asn2, adn2, h2, b2, out2, bns2, N2, (2 * N2) / 1024,
                              g2, be2, pw2, sc2, sh2, w2a, 1.0f / N2, cnt2);
    pool_score<<<N2 / 32, 256>>>(out2, w2a, score2, N2);
    topk_select<<<BT, 512>>>(score2, KP1, KP2, gidx2, tanh2, nullptr);
    readout_s1<<<dim3(BT, 8), 256>>>(out2, sc2, sh2, gidx2, tanh2, KP2, part2);

    // ---- final (join side stream) ----
    cudaStreamWaitEvent(0, ev5, 0);
    final_linear<<<BT, 256>>>(part, part2, Wl, bl, out);
}